// round 12
// baseline (speedup 1.0000x reference)
#include <cuda_runtime.h>
#include <cuda_fp16.h>
#include <math.h>
#include <stdint.h>

#define N    8192
#define D    256
#define INV_T (1.0f / 0.7f)
#define EX2SC (1.44269504088896f * INV_T)   // log2(e)/T

#define TM 128
#define TN 128
#define GI (N / TM)                  // 64
#define NTILES (GI * (GI + 1) / 2)   // 2080

// ---------------- device scratch ----------------
__device__ __half g_Ph[N * D];       // normalized rows, f16, row-major
__device__ float g_A[N];
__device__ float g_B[N];
__device__ float g_selfsim[N];
__device__ int   g_cls[N];

// ---------------- helpers ----------------
__device__ __forceinline__ uint32_t smem_u32(const void* p) {
    uint32_t a;
    asm("{ .reg .u64 t; cvta.to.shared.u64 t, %1; cvt.u32.u64 %0, t; }"
        : "=r"(a) : "l"(p));
    return a;
}
#define SW128(off) ((off) ^ (((off) >> 3) & 0x70))
#define BAR1() asm volatile("bar.sync 1, 256;" ::: "memory")
#define BAR2() asm volatile("bar.sync 2, 128;" ::: "memory")

__device__ __forceinline__ void cp16(uint32_t dst, const void* src) {
    asm volatile("cp.async.cg.shared.global [%0], [%1], 16;" :: "r"(dst), "l"(src));
}
__device__ __forceinline__ void cp_commit() {
    asm volatile("cp.async.commit_group;" ::: "memory");
}
__device__ __forceinline__ void ldsm4(uint32_t& r0, uint32_t& r1,
                                      uint32_t& r2, uint32_t& r3, uint32_t addr) {
    asm volatile("ldmatrix.sync.aligned.m8n8.x4.shared.b16 {%0,%1,%2,%3}, [%4];"
                 : "=r"(r0), "=r"(r1), "=r"(r2), "=r"(r3) : "r"(addr));
}
__device__ __forceinline__ void lds64(uint32_t& lo, uint32_t& hi, uint32_t addr) {
    asm volatile("ld.shared.v2.b32 {%0,%1}, [%2];" : "=r"(lo), "=r"(hi) : "r"(addr));
}
__device__ __forceinline__ void mma16816h(uint32_t* d, const uint32_t* a,
                                          const uint32_t* b) {
    asm volatile("mma.sync.aligned.m16n8k16.row.col.f16.f16.f16.f16 "
                 "{%0,%1}, {%2,%3,%4,%5}, {%6,%7}, {%0,%1};"
                 : "+r"(d[0]), "+r"(d[1])
                 : "r"(a[0]), "r"(a[1]), "r"(a[2]), "r"(a[3]),
                   "r"(b[0]), "r"(b[1]));
}
__device__ __forceinline__ float ex2(float x) {
    float r;
    asm("ex2.approx.f32 %0, %1;" : "=f"(r) : "f"(x));
    return r;
}

// ---------------- SMEM layout ----------------
// HMMA: 4 resident chunks A/B (SW128), then FFMA: 2 dbl-buffered pad-144 chunks
#define ACH(c)  ((c) * 16384)
#define BCH(c)  (65536 + (c) * 16384)
#define CLSI_OFF  131072
#define CLSJ_OFF  131584
#define SACCI_OFF 132096
#define SBCCI_OFF 132608
#define SACCJ_OFF 133120
#define SBCCJ_OFF 133632
#define A2CH(p) (134144 + (p) * 18432)          // 128 rows x 144 B
#define B2CH(p) (171008 + (p) * 18432)
#define CLSI2_OFF  207872
#define CLSJ2_OFF  208384
#define SACCI2_OFF 208896
#define SBCCI2_OFF 209408
#define SACCJ2_OFF 209920
#define SBCCJ2_OFF 210432
#define SMEM_BYTES 210944

// ---------------------------------------------------------------------------
// k_norm: dtype detect + zero A/B + normalize->f16 + selfsim + class
// 4 rows per warp, loads batched for MLP=8.
// ---------------------------------------------------------------------------
__global__ void k_norm(const float* __restrict__ P, const void* __restrict__ yv) {
    __shared__ int s_is64;
    const int tid  = threadIdx.x;
    const int w    = tid >> 5;
    const int lane = tid & 31;
    const int rowBase = blockIdx.x * 32 + w * 4;

    if (w == 0) {   // detect: int64 y<10 => all odd 32-bit words zero
        int v = ((const int*)yv)[2 * lane + 1];
        unsigned any = __ballot_sync(0xffffffffu, v != 0);
        if (lane == 0) s_is64 = (any == 0) ? 1 : 0;
    }
    if (blockIdx.x < 32) {
        int idx = blockIdx.x * 256 + tid;
        g_A[idx] = 0.0f; g_B[idx] = 0.0f;
    }
    __syncthreads();
    const int is64 = s_is64;

    float4 v[4][2];
    #pragma unroll
    for (int r = 0; r < 4; r++) {
        const float4* p4 = (const float4*)(P + (size_t)(rowBase + r) * D);
        v[r][0] = p4[lane];
        v[r][1] = p4[lane + 32];
    }

    #pragma unroll
    for (int r = 0; r < 4; r++) {
        const int row = rowBase + r;
        float ss = v[r][0].x*v[r][0].x + v[r][0].y*v[r][0].y
                 + v[r][0].z*v[r][0].z + v[r][0].w*v[r][0].w
                 + v[r][1].x*v[r][1].x + v[r][1].y*v[r][1].y
                 + v[r][1].z*v[r][1].z + v[r][1].w*v[r][1].w;
        #pragma unroll
        for (int o = 16; o; o >>= 1) ss += __shfl_xor_sync(0xffffffffu, ss, o);
        float rn = rsqrtf(ss);

        __half h[8];
        h[0] = __float2half_rn(v[r][0].x * rn); h[1] = __float2half_rn(v[r][0].y * rn);
        h[2] = __float2half_rn(v[r][0].z * rn); h[3] = __float2half_rn(v[r][0].w * rn);
        h[4] = __float2half_rn(v[r][1].x * rn); h[5] = __float2half_rn(v[r][1].y * rn);
        h[6] = __float2half_rn(v[r][1].z * rn); h[7] = __float2half_rn(v[r][1].w * rn);

        float sb = 0.0f;
        #pragma unroll
        for (int q = 0; q < 8; q++) { float f = __half2float(h[q]); sb += f * f; }
        #pragma unroll
        for (int o = 16; o; o >>= 1) sb += __shfl_xor_sync(0xffffffffu, sb, o);

        *(uint2*)(g_Ph + (size_t)row * D + lane * 4)       = *(uint2*)&h[0];
        *(uint2*)(g_Ph + (size_t)row * D + 128 + lane * 4) = *(uint2*)&h[4];

        if (lane == 0) {
            int c = is64 ? (int)((const long long*)yv)[row] : ((const int*)yv)[row];
            g_cls[row]     = c;
            g_selfsim[row] = sb;
        }
    }
}

// ---------------------------------------------------------------------------
__device__ __forceinline__ void map_tile(int t, int& bi, int& bj) {
    int b = 0, r = t;
    #pragma unroll 1
    while (r >= GI - b) { r -= GI - b; b++; }
    bi = b; bj = b + r;
}

// ---------------- HMMA side loaders ----------------
__device__ __forceinline__ void issue_chunk(uint32_t sbase, int ck,
                                            int iBase, int jBase, int tid) {
    #pragma unroll
    for (int q = 0; q < 4; q++) {
        int s  = tid + q * 256;
        int r  = s >> 3;
        int sg = s & 7;
        uint32_t soff = SW128((uint32_t)(r * 128 + sg * 16));
        cp16(sbase + ACH(ck) + soff, g_Ph + (size_t)(iBase + r) * D + ck * 64 + sg * 8);
        cp16(sbase + BCH(ck) + soff, g_Ph + (size_t)(jBase + r) * D + ck * 64 + sg * 8);
    }
    cp_commit();
}

__device__ __forceinline__ void load_frags(uint32_t aB, uint32_t bB, int ks,
                                           int m0, int n0, int lrow, int lkoff,
                                           uint32_t afr[4][4], uint32_t bfr[4][2]) {
    #pragma unroll
    for (int nf2 = 0; nf2 < 2; nf2++) {
        uint32_t r0, r1, r2, r3;
        uint32_t off = (uint32_t)((n0 + nf2 * 16 + lrow) * 128 + lkoff + ks * 32);
        ldsm4(r0, r1, r2, r3, bB + SW128(off));
        bfr[nf2 * 2 + 0][0] = r0; bfr[nf2 * 2 + 0][1] = r2;
        bfr[nf2 * 2 + 1][0] = r1; bfr[nf2 * 2 + 1][1] = r3;
    }
    #pragma unroll
    for (int mf = 0; mf < 4; mf++) {
        uint32_t off = (uint32_t)((m0 + mf * 16 + lrow) * 128 + lkoff + ks * 32);
        ldsm4(afr[mf][0], afr[mf][1], afr[mf][2], afr[mf][3], aB + SW128(off));
    }
}

__device__ __forceinline__ void compute_chunk(uint32_t sbase, int ck,
                                              int m0, int n0, int lrow, int lkoff,
                                              uint32_t afr[2][4][4],
                                              uint32_t bfr[2][4][2],
                                              uint32_t acc[4][4][2]) {
    const uint32_t aB = sbase + ACH(ck);
    const uint32_t bB = sbase + BCH(ck);
    load_frags(aB, bB, 0, m0, n0, lrow, lkoff, afr[0], bfr[0]);
    #pragma unroll
    for (int ks = 0; ks < 4; ks++) {
        const int cur = ks & 1;
        if (ks < 3)
            load_frags(aB, bB, ks + 1, m0, n0, lrow, lkoff, afr[cur ^ 1], bfr[cur ^ 1]);
        #pragma unroll
        for (int mf = 0; mf < 4; mf++)
            #pragma unroll
            for (int nf = 0; nf < 4; nf++)
                mma16816h(acc[mf][nf], afr[cur][mf], bfr[cur][nf]);
    }
}

// ---------------- FFMA side loaders ----------------
__device__ __forceinline__ void issue_chunk2(uint32_t sbase, int p, int ck,
                                             int iBase, int jBase, int t) {
    #pragma unroll
    for (int q = 0; q < 8; q++) {
        int s  = t + q * 128;
        int r  = s >> 3;
        int sg = s & 7;
        cp16(sbase + A2CH(p) + r * 144 + sg * 16,
             g_Ph + (size_t)(iBase + r) * D + ck * 64 + sg * 8);
        cp16(sbase + B2CH(p) + r * 144 + sg * 16,
             g_Ph + (size_t)(jBase + r) * D + ck * 64 + sg * 8);
    }
    cp_commit();
}

__device__ __forceinline__ void ffma_compute(uint32_t sbase, int p, int tmg, int tn,
                                             int half, __half2 acc[8][8]) {
    const uint32_t aBase = sbase + A2CH(p) + tmg * 144;
    const uint32_t bBase = sbase + B2CH(p) + (half * 64 + tn) * 144;
    #pragma unroll 2
    for (int k4 = 0; k4 < 16; k4++) {
        uint32_t av[8][2], bv[8][2];
        #pragma unroll
        for (int m = 0; m < 8; m++)
            lds64(av[m][0], av[m][1], aBase + m * (16 * 144) + k4 * 8);
        #pragma unroll
        for (int n = 0; n < 8; n++)
            lds64(bv[n][0], bv[n][1], bBase + n * (8 * 144) + k4 * 8);
        #pragma unroll
        for (int kk = 0; kk < 2; kk++)
            #pragma unroll
            for (int m = 0; m < 8; m++)
                #pragma unroll
                for (int n = 0; n < 8; n++)
                    acc[m][n] = __hfma2(*(__half2*)&av[m][kk],
                                        *(__half2*)&bv[n][kk], acc[m][n]);
    }
}

// ---------------------------------------------------------------------------
// k_main: warps 0-7 HMMA tiles [0,TSPLIT), warps 8-11 HFMA2 tiles [TSPLIT,2080)
// ---------------------------------------------------------------------------
__global__ void __launch_bounds__(384, 1) k_main() {
    extern __shared__ __align__(128) unsigned char smem[];
    const uint32_t sbase = smem_u32(smem);
    const int tid  = threadIdx.x;
    const int wid  = tid >> 5;
    const int lane = tid & 31;
    const int bid  = blockIdx.x;
    const int STR  = gridDim.x;
    const int TSPLIT = NTILES - 2 * STR;

    if (tid < 256) {
        // =========================== HMMA worker ===========================
        int*   clsI  = (int*)(smem + CLSI_OFF);
        int*   clsJ  = (int*)(smem + CLSJ_OFF);
        float* sAccI = (float*)(smem + SACCI_OFF);
        float* sBccI = (float*)(smem + SBCCI_OFF);
        float* sAccJ = (float*)(smem + SACCJ_OFF);
        float* sBccJ = (float*)(smem + SBCCJ_OFF);

        int tile = bid;
        int biBlk, bjBlk;
        map_tile(tile, biBlk, bjBlk);
        int iBase = biBlk * TM;
        int jBase = bjBlk * TN;
        bool offdiag = (biBlk != bjBlk);

        if (tid < 128) {
            clsI[tid] = g_cls[iBase + tid];
            sAccI[tid] = 0.0f; sBccI[tid] = 0.0f;
            sAccJ[tid] = 0.0f; sBccJ[tid] = 0.0f;
        } else {
            clsJ[tid - 128] = g_cls[jBase + tid - 128];
        }
        #pragma unroll
        for (int ck = 0; ck < 4; ck++) issue_chunk(sbase, ck, iBase, jBase, tid);

        const int m0 = (wid >> 2) * 64;
        const int n0 = (wid & 3) * 32;
        const int lrow  = lane & 15;
        const int lkoff = (lane >> 4) * 16;
        const int gl   = lane >> 2;
        const int quad = lane & 3;

        #pragma unroll 1
        while (true) {
            int ntile = tile + STR;
            const bool last = (ntile >= TSPLIT);
            int nbi, nbj;
            if (last) { nbi = biBlk; nbj = bjBlk; }
            else      map_tile(ntile, nbi, nbj);
            const int niBase = nbi * TM;
            const int njBase = nbj * TN;

            uint32_t acc[4][4][2];
            #pragma unroll
            for (int mf = 0; mf < 4; mf++)
                #pragma unroll
                for (int nf = 0; nf < 4; nf++) { acc[mf][nf][0] = 0u; acc[mf][nf][1] = 0u; }

            uint32_t afr[2][4][4], bfr[2][4][2];

            asm volatile("cp.async.wait_group 3;" ::: "memory");
            BAR1();
            compute_chunk(sbase, 0, m0, n0, lrow, lkoff, afr, bfr, acc);
            asm volatile("cp.async.wait_group 2;" ::: "memory");
            BAR1();
            issue_chunk(sbase, 0, niBase, njBase, tid);
            compute_chunk(sbase, 1, m0, n0, lrow, lkoff, afr, bfr, acc);
            asm volatile("cp.async.wait_group 2;" ::: "memory");
            BAR1();
            issue_chunk(sbase, 1, niBase, njBase, tid);
            compute_chunk(sbase, 2, m0, n0, lrow, lkoff, afr, bfr, acc);
            asm volatile("cp.async.wait_group 2;" ::: "memory");
            BAR1();
            issue_chunk(sbase, 2, niBase, njBase, tid);
            compute_chunk(sbase, 3, m0, n0, lrow, lkoff, afr, bfr, acc);

            // ---- epilogue ----
            int cjr[8];
            #pragma unroll
            for (int q = 0; q < 8; q++)
                cjr[q] = clsJ[n0 + (q >> 1) * 8 + quad * 2 + (q & 1)];

            float aCol[8], bCol[8];
            #pragma unroll
            for (int q = 0; q < 8; q++) { aCol[q] = 0.0f; bCol[q] = 0.0f; }

            #pragma unroll
            for (int rr = 0; rr < 2; rr++) {
                #pragma unroll
                for (int mf = 0; mf < 4; mf++) {
                    const int rl = m0 + mf * 16 + gl + rr * 8;
                    const int ci = clsI[rl];
                    float aRow = 0.0f, bRow = 0.0f;
                    #pragma unroll
                    for (int q = 0; q < 8; q++) {
                        const int nf = q >> 1;
                        float2 pr = __half22float2(*(const __half2*)&acc[mf][nf][rr]);
                        const float s = (q & 1) ? pr.y : pr.x;
                        const bool same = (ci == cjr[q]);
                        const float v = ex2(s * (same ? -EX2SC : EX2SC));
                        const float va = same ? 0.0f : v;
                        const float vb = v - va;
                        aRow += va; bRow += vb;
                        aCol[q] += va; bCol[q] += vb;
                    }
                    aRow += __shfl_xor_sync(0xffffffffu, aRow, 1);
                    aRow += __shfl_xor_sync(0xffffffffu, aRow, 2);
                    bRow += __shfl_xor_sync(0xffffffffu, bRow, 1);
                    bRow += __shfl_xor_sync(0xffffffffu, bRow, 2);
                    if (quad == 0) {
                        atomicAdd(&sAccI[rl], aRow);
                        atomicAdd(&sBccI[rl], bRow);
                    }
                }
            }

            if (offdiag) {
                #pragma unroll
                for (int q = 0; q < 8; q++) {
                    float a = aCol[q], b = bCol[q];
                    #pragma unroll
                    for (int o = 4; o <= 16; o <<= 1) {
                        a += __shfl_xor_sync(0xffffffffu, a, o);
                        b += __shfl_xor_sync(0xffffffffu, b, o);
                    }
                    if (lane < 4) {
                        const int cl = n0 + (q >> 1) * 8 + quad * 2 + (q & 1);
                        atomicAdd(&sAccJ[cl], a);
                        atomicAdd(&sBccJ[cl], b);
                    }
                }
            }

            BAR1();
            issue_chunk(sbase, 3, niBase, njBase, tid);

            if (tid < 128) {
                atomicAdd(&g_A[iBase + tid], sAccI[tid]);
                atomicAdd(&g_B[iBase + tid], sBccI[tid]);
                if (offdiag) {
                    atomicAdd(&g_A[jBase + tid], sAccJ[tid]);
                    atomicAdd(&g_B[jBase + tid], sBccJ[tid]);
                }
                sAccI[tid] = 0.0f; sBccI[tid] = 0.0f;
                sAccJ[tid] = 0.0f; sBccJ[tid] = 0.0f;
                clsI[tid] = g_cls[niBase + tid];
            } else {
                clsJ[tid - 128] = g_cls[njBase + tid - 128];
            }

            if (last) break;
            tile = ntile; biBlk = nbi; bjBlk = nbj;
            iBase = niBase; jBase = njBase;
            offdiag = (nbi != nbj);
        }
    } else {
        // =========================== FFMA worker ===========================
        int*   clsI2  = (int*)(smem + CLSI2_OFF);
        int*   clsJ2  = (int*)(smem + CLSJ2_OFF);
        float* sAccI2 = (float*)(smem + SACCI2_OFF);
        float* sBccI2 = (float*)(smem + SBCCI2_OFF);
        float* sAccJ2 = (float*)(smem + SACCJ2_OFF);
        float* sBccJ2 = (float*)(smem + SBCCJ2_OFF);

        const int t   = tid - 256;    // 0..127
        const int tn  = t & 7;
        const int tmg = t >> 3;       // 0..15
        const int ln  = t & 31;

        int tile = TSPLIT + bid;
        int biB, bjB;
        map_tile(tile, biB, bjB);
        int iB = biB * TM, jB = bjB * TN;
        bool offd = (biB != bjB);

        clsI2[t] = g_cls[iB + t];
        clsJ2[t] = g_cls[jB + t];
        sAccI2[t] = 0.0f; sBccI2[t] = 0.0f;
        sAccJ2[t] = 0.0f; sBccJ2[t] = 0.0f;

        issue_chunk2(sbase, 0, 0, iB, jB, t);
        issue_chunk2(sbase, 1, 1, iB, jB, t);

        #pragma unroll 1
        while (true) {
            int nt = tile + STR;
            const bool lastT = (nt >= NTILES);
            int nbi, nbj;
            if (lastT) { nbi = biB; nbj = bjB; }
            else       map_tile(nt, nbi, nbj);
            const int niB = nbi * TM, njB = nbj * TN;

            #pragma unroll 1
            for (int half = 0; half < 2; half++) {
                __half2 acc[8][8];
                #pragma unroll
                for (int m = 0; m < 8; m++)
                    #pragma unroll
                    for (int n = 0; n < 8; n++) acc[m][n] = __float2half2_rn(0.0f);

                #pragma unroll 1
                for (int ck = 0; ck < 4; ck++) {
                    asm volatile("cp.async.wait_group 1;" ::: "memory");
                    BAR2();
                    ffma_compute(sbase, ck & 1, tmg, tn, half, acc);
                    BAR2();
                    int ns = half * 4 + ck + 2;
                    const bool nx = (ns >= 8);
                    issue_chunk2(sbase, ns & 1, ns & 3, nx ? niB : iB, nx ? njB : jB, t);
                }

                // ---- epilogue for this half ----
                float colA[8], colB[8];
                #pragma unroll
                for (int n = 0; n < 8; n++) { colA[n] = 0.0f; colB[n] = 0.0f; }

                #pragma unroll
                for (int m = 0; m < 8; m++) {
                    const int rl = tmg + 16 * m;
                    const int ci = clsI2[rl];
                    float rA = 0.0f, rB = 0.0f;
                    #pragma unroll
                    for (int n = 0; n < 8; n++) {
                        const int cl = half * 64 + tn + 8 * n;
                        const int cj = clsJ2[cl];
                        float2 f = __half22float2(acc[m][n]);
                        const float s = f.x + f.y;
                        const bool same = (ci == cj);
                        const float v = ex2(s * (same ? -EX2SC : EX2SC));
                        const float va = same ? 0.0f : v;
                        const float vb = v - va;
                        rA += va; rB += vb;
                        colA[n] += va; colB[n] += vb;
                    }
                    rA += __shfl_xor_sync(0xffffffffu, rA, 1);
                    rA += __shfl_xor_sync(0xffffffffu, rA, 2);
                    rA += __shfl_xor_sync(0xffffffffu, rA, 4);
                    rB += __shfl_xor_sync(0xffffffffu, rB, 1);
                    rB += __shfl_xor_sync(0xffffffffu, rB, 2);
                    rB += __shfl_xor_sync(0xffffffffu, rB, 4);
                    if (tn == 0) {
                        atomicAdd(&sAccI2[rl], rA);
                        atomicAdd(&sBccI2[rl], rB);
                    }
                }
                if (offd) {
                    #pragma unroll
                    for (int n = 0; n < 8; n++) {
                        float a = colA[n], b = colB[n];
                        a += __shfl_xor_sync(0xffffffffu, a, 8);
                        a += __shfl_xor_sync(0xffffffffu, a, 16);
                        b += __shfl_xor_sync(0xffffffffu, b, 8);
                        b += __shfl_xor_sync(0xffffffffu, b, 16);
                        if (ln < 8) {
                            const int cl = half * 64 + tn + 8 * n;
                            atomicAdd(&sAccJ2[cl], a);
                            atomicAdd(&sBccJ2[cl], b);
                        }
                    }
                }
            }

            BAR2();
            atomicAdd(&g_A[iB + t], sAccI2[t]);
            atomicAdd(&g_B[iB + t], sBccI2[t]);
            if (offd) {
                atomicAdd(&g_A[jB + t], sAccJ2[t]);
                atomicAdd(&g_B[jB + t], sBccJ2[t]);
            }
            sAccI2[t] = 0.0f; sBccI2[t] = 0.0f;
            sAccJ2[t] = 0.0f; sBccJ2[t] = 0.0f;

            if (lastT) break;
            tile = nt; biB = nbi; bjB = nbj; iB = niB; jB = njB;
            offd = (biB != bjB);
            clsI2[t] = g_cls[iB + t];
            clsJ2[t] = g_cls[jB + t];
            BAR2();
        }
    }
}

// ---------------------------------------------------------------------------
// k_loss: histogram, subtract self term (f16-rounded), empty-set, mean
// ---------------------------------------------------------------------------
__global__ void k_loss(float* __restrict__ out) {
    __shared__ float red[256];
    __shared__ int hist[16];
    const int tid = threadIdx.x;
    if (tid < 16) hist[tid] = 0;
    __syncthreads();
    for (int r = tid; r < N; r += 256) atomicAdd(&hist[g_cls[r] & 15], 1);
    __syncthreads();

    const float MF = __expf(0.5f * INV_T);
    float sum = 0.0f;
    for (int r = tid; r < N; r += 256) {
        int   c   = g_cls[r] & 15;
        int   cnt = hist[c];
        float ssh = __half2float(__float2half_rn(g_selfsim[r]));
        float Bv  = g_B[r] - __expf(-ssh * INV_T);
        float Av  = (N - cnt > 0) ? g_A[r] : 1.0f;
        Bv        = (cnt - 1 > 0) ? Bv : 1.0f;
        sum += log1pf(MF * Av * Bv);
    }
    red[tid] = sum;
    __syncthreads();
    #pragma unroll
    for (int s = 128; s; s >>= 1) {
        if (tid < s) red[tid] += red[tid + s];
        __syncthreads();
    }
    if (tid == 0) out[0] = red[0] / (float)N;
}

// ---------------------------------------------------------------------------
extern "C" void kernel_launch(void* const* d_in, const int* in_sizes, int n_in,
                              void* d_out, int out_size) {
    const float* P = (const float*)d_in[0];
    const void*  y = d_in[1];
    float*     out = (float*)d_out;

    cudaFuncSetAttribute(k_main, cudaFuncAttributeMaxDynamicSharedMemorySize,
                         SMEM_BYTES);

    int sms = 148;
    cudaDeviceGetAttribute(&sms, cudaDevAttrMultiProcessorCount, 0);

    k_norm<<<N / 32, 256>>>(P, y);
    k_main<<<sms, 384, SMEM_BYTES>>>();
    k_loss<<<1, 256>>>(out);
}

// round 13
// speedup vs baseline: 1.3257x; 1.3257x over previous
#include <cuda_runtime.h>
#include <cuda_fp16.h>
#include <math.h>
#include <stdint.h>

#define N    8192
#define D    256
#define INV_T (1.0f / 0.7f)
#define EX2SC (1.44269504088896f * INV_T)   // log2(e)/T

#define TM 128
#define TN 128
#define GI (N / TM)                  // 64
#define NTILES (GI * (GI + 1) / 2)   // 2080

// ---------------- device scratch ----------------
__device__ __half g_Ph[N * D];       // normalized rows, f16, row-major
__device__ float g_A[N];
__device__ float g_B[N];
__device__ float g_selfsim[N];
__device__ int   g_cls[N];

// ---------------- helpers ----------------
__device__ __forceinline__ uint32_t smem_u32(const void* p) {
    uint32_t a;
    asm("{ .reg .u64 t; cvta.to.shared.u64 t, %1; cvt.u32.u64 %0, t; }"
        : "=r"(a) : "l"(p));
    return a;
}
#define SW128(off) ((off) ^ (((off) >> 3) & 0x70))

__device__ __forceinline__ void cp16(uint32_t dst, const void* src) {
    asm volatile("cp.async.cg.shared.global [%0], [%1], 16;" :: "r"(dst), "l"(src));
}
__device__ __forceinline__ void cp_commit() {
    asm volatile("cp.async.commit_group;" ::: "memory");
}
__device__ __forceinline__ void ldsm4(uint32_t& r0, uint32_t& r1,
                                      uint32_t& r2, uint32_t& r3, uint32_t addr) {
    asm volatile("ldmatrix.sync.aligned.m8n8.x4.shared.b16 {%0,%1,%2,%3}, [%4];"
                 : "=r"(r0), "=r"(r1), "=r"(r2), "=r"(r3) : "r"(addr));
}
__device__ __forceinline__ void mma16816h(uint32_t* d, const uint32_t* a,
                                          const uint32_t* b) {
    asm volatile("mma.sync.aligned.m16n8k16.row.col.f16.f16.f16.f16 "
                 "{%0,%1}, {%2,%3,%4,%5}, {%6,%7}, {%0,%1};"
                 : "+r"(d[0]), "+r"(d[1])
                 : "r"(a[0]), "r"(a[1]), "r"(a[2]), "r"(a[3]),
                   "r"(b[0]), "r"(b[1]));
}
__device__ __forceinline__ float ex2(float x) {
    float r;
    asm("ex2.approx.f32 %0, %1;" : "=f"(r) : "f"(x));
    return r;
}

// ---------------- SMEM layout: 3-deep ring of (A16KB + B16KB) chunks --------
#define ACH(b) ((b) * 16384)                 // A buf b: 128 rows x 128 B (SW128)
#define BCH(b) (49152 + (b) * 16384)         // B buf b
#define CLSI_OFF  98304
#define CLSJ_OFF  98816
#define SACCI_OFF 99328
#define SBCCI_OFF 99840
#define SACCJ_OFF 100352
#define SBCCJ_OFF 100864
#define SMEM_BYTES 101376                    // x2 CTAs = 202752 B/SM

// ---------------------------------------------------------------------------
// k_norm: dtype detect + zero A/B + normalize->f16 + selfsim + class
// ---------------------------------------------------------------------------
__global__ void k_norm(const float* __restrict__ P, const void* __restrict__ yv) {
    __shared__ int s_is64;
    const int tid  = threadIdx.x;
    const int w    = tid >> 5;
    const int lane = tid & 31;
    const int row  = blockIdx.x * 8 + w;

    if (w == 0) {   // detect: int64 y<10 => all odd 32-bit words zero
        int v = ((const int*)yv)[2 * lane + 1];
        unsigned any = __ballot_sync(0xffffffffu, v != 0);
        if (lane == 0) s_is64 = (any == 0) ? 1 : 0;
    }
    if (blockIdx.x < 32) {              // zero accumulators
        int idx = blockIdx.x * 256 + tid;
        g_A[idx] = 0.0f; g_B[idx] = 0.0f;
    }
    __syncthreads();
    const int is64 = s_is64;

    const float4* p4 = (const float4*)(P + (size_t)row * D);
    float4 v0 = p4[lane];
    float4 v1 = p4[lane + 32];

    float ss = v0.x*v0.x + v0.y*v0.y + v0.z*v0.z + v0.w*v0.w
             + v1.x*v1.x + v1.y*v1.y + v1.z*v1.z + v1.w*v1.w;
    #pragma unroll
    for (int o = 16; o; o >>= 1) ss += __shfl_xor_sync(0xffffffffu, ss, o);
    float rn = rsqrtf(ss);

    __half h[8];
    h[0] = __float2half_rn(v0.x * rn); h[1] = __float2half_rn(v0.y * rn);
    h[2] = __float2half_rn(v0.z * rn); h[3] = __float2half_rn(v0.w * rn);
    h[4] = __float2half_rn(v1.x * rn); h[5] = __float2half_rn(v1.y * rn);
    h[6] = __float2half_rn(v1.z * rn); h[7] = __float2half_rn(v1.w * rn);

    float sb = 0.0f;
    #pragma unroll
    for (int q = 0; q < 8; q++) { float f = __half2float(h[q]); sb += f * f; }
    #pragma unroll
    for (int o = 16; o; o >>= 1) sb += __shfl_xor_sync(0xffffffffu, sb, o);

    *(uint2*)(g_Ph + (size_t)row * D + lane * 4)       = *(uint2*)&h[0];
    *(uint2*)(g_Ph + (size_t)row * D + 128 + lane * 4) = *(uint2*)&h[4];

    if (lane == 0) {
        int c = is64 ? (int)((const long long*)yv)[row] : ((const int*)yv)[row];
        g_cls[row]     = c;
        g_selfsim[row] = sb;
    }
}

// ---------------------------------------------------------------------------
__device__ __forceinline__ void map_tile(int t, int& bi, int& bj) {
    int b = 0, r = t;
    #pragma unroll 1
    while (r >= GI - b) { r -= GI - b; b++; }
    bi = b; bj = b + r;
}

__device__ __forceinline__ void issue_chunk(uint32_t sbase, int buf, int ck,
                                            int iBase, int jBase, int tid) {
    #pragma unroll
    for (int q = 0; q < 4; q++) {
        int s  = tid + q * 256;
        int r  = s >> 3;
        int sg = s & 7;
        uint32_t soff = SW128((uint32_t)(r * 128 + sg * 16));
        cp16(sbase + ACH(buf) + soff, g_Ph + (size_t)(iBase + r) * D + ck * 64 + sg * 8);
        cp16(sbase + BCH(buf) + soff, g_Ph + (size_t)(jBase + r) * D + ck * 64 + sg * 8);
    }
    cp_commit();
}

__device__ __forceinline__ void compute_chunk(uint32_t sbase, int buf,
                                              int m0, int n0, int lrow, int lkoff,
                                              uint32_t acc[4][4][2]) {
    const uint32_t aB = sbase + ACH(buf);
    const uint32_t bB = sbase + BCH(buf);
    #pragma unroll
    for (int ks = 0; ks < 4; ks++) {
        uint32_t afr[4][4], bfr[4][2];
        #pragma unroll
        for (int nf2 = 0; nf2 < 2; nf2++) {
            uint32_t r0, r1, r2, r3;
            uint32_t off = (uint32_t)((n0 + nf2 * 16 + lrow) * 128 + lkoff + ks * 32);
            ldsm4(r0, r1, r2, r3, bB + SW128(off));
            bfr[nf2 * 2 + 0][0] = r0; bfr[nf2 * 2 + 0][1] = r2;
            bfr[nf2 * 2 + 1][0] = r1; bfr[nf2 * 2 + 1][1] = r3;
        }
        #pragma unroll
        for (int mf = 0; mf < 4; mf++) {
            uint32_t off = (uint32_t)((m0 + mf * 16 + lrow) * 128 + lkoff + ks * 32);
            ldsm4(afr[mf][0], afr[mf][1], afr[mf][2], afr[mf][3], aB + SW128(off));
        }
        #pragma unroll
        for (int mf = 0; mf < 4; mf++)
            #pragma unroll
            for (int nf = 0; nf < 4; nf++)
                mma16816h(acc[mf][nf], afr[mf], bfr[nf]);
    }
}

// ---------------------------------------------------------------------------
// k_main: persistent, 2 CTAs/SM, 3-deep cross-tile cp.async ring, f16 MMA
// ---------------------------------------------------------------------------
__global__ void __launch_bounds__(256, 2) k_main() {
    extern __shared__ __align__(128) unsigned char smem[];
    const uint32_t sbase = smem_u32(smem);
    const int tid  = threadIdx.x;
    const int wid  = tid >> 5;
    const int lane = tid & 31;
    const int STR  = gridDim.x;

    int*   clsI  = (int*)(smem + CLSI_OFF);
    int*   clsJ  = (int*)(smem + CLSJ_OFF);
    float* sAccI = (float*)(smem + SACCI_OFF);
    float* sBccI = (float*)(smem + SBCCI_OFF);
    float* sAccJ = (float*)(smem + SACCJ_OFF);
    float* sBccJ = (float*)(smem + SBCCJ_OFF);

    int tile = blockIdx.x;
    if (tile >= NTILES) return;

    int biBlk, bjBlk;
    map_tile(tile, biBlk, bjBlk);
    int iBase = biBlk * TM;
    int jBase = bjBlk * TN;
    bool offdiag = (biBlk != bjBlk);

    if (tid < 128) {
        clsI[tid] = g_cls[iBase + tid];
        sAccI[tid] = 0.0f; sBccI[tid] = 0.0f;
        sAccJ[tid] = 0.0f; sBccJ[tid] = 0.0f;
    } else {
        clsJ[tid - 128] = g_cls[jBase + tid - 128];
    }

    // ---- issue cursor (3 chunk-groups always in flight; dummy tail) ----
    int issTile = tile, issIB = iBase, issJB = jBase, issCk = 0;
    int ibuf = 0, cbuf = 0;
    #pragma unroll
    for (int p = 0; p < 3; p++) {
        issue_chunk(sbase, ibuf, issCk, issIB, issJB, tid);
        ibuf = (ibuf == 2) ? 0 : ibuf + 1;
        if (++issCk == 4) {
            issCk = 0;
            issTile += STR;
            if (issTile < NTILES) {
                int a, b; map_tile(issTile, a, b);
                issIB = a * TM; issJB = b * TN;
            }
        }
    }

    const int m0 = (wid >> 2) * 64;
    const int n0 = (wid & 3) * 32;
    const int lrow  = lane & 15;
    const int lkoff = (lane >> 4) * 16;
    const int gl   = lane >> 2;
    const int quad = lane & 3;

    #pragma unroll 1
    while (true) {
        const int ntile = tile + STR;
        const bool last = (ntile >= NTILES);

        uint32_t acc[4][4][2];
        #pragma unroll
        for (int mf = 0; mf < 4; mf++)
            #pragma unroll
            for (int nf = 0; nf < 4; nf++) { acc[mf][nf][0] = 0u; acc[mf][nf][1] = 0u; }

        #pragma unroll 1
        for (int ck = 0; ck < 4; ck++) {
            asm volatile("cp.async.wait_group 2;" ::: "memory");
            __syncthreads();                       // chunk data visible to all
            compute_chunk(sbase, cbuf, m0, n0, lrow, lkoff, acc);
            cbuf = (cbuf == 2) ? 0 : cbuf + 1;
            __syncthreads();                       // all done reading freed buf
            issue_chunk(sbase, ibuf, issCk, issIB, issJB, tid);
            ibuf = (ibuf == 2) ? 0 : ibuf + 1;
            if (++issCk == 4) {
                issCk = 0;
                issTile += STR;
                if (issTile < NTILES) {
                    int a, b; map_tile(issTile, a, b);
                    issIB = a * TM; issJB = b * TN;
                }
            }
        }

        // ---- epilogue: unpack f16 acc, masked exp sums ----
        int cjr[8];
        #pragma unroll
        for (int q = 0; q < 8; q++)
            cjr[q] = clsJ[n0 + (q >> 1) * 8 + quad * 2 + (q & 1)];

        float aCol[8], bCol[8];
        #pragma unroll
        for (int q = 0; q < 8; q++) { aCol[q] = 0.0f; bCol[q] = 0.0f; }

        #pragma unroll
        for (int rr = 0; rr < 2; rr++) {
            #pragma unroll
            for (int mf = 0; mf < 4; mf++) {
                const int rl = m0 + mf * 16 + gl + rr * 8;
                const int ci = clsI[rl];
                float aRow = 0.0f, bRow = 0.0f;
                #pragma unroll
                for (int q = 0; q < 8; q++) {
                    const int nf = q >> 1;
                    float2 pr = __half22float2(*(const __half2*)&acc[mf][nf][rr]);
                    const float s = (q & 1) ? pr.y : pr.x;
                    const bool same = (ci == cjr[q]);
                    const float v = ex2(s * (same ? -EX2SC : EX2SC));
                    const float va = same ? 0.0f : v;
                    const float vb = v - va;
                    aRow += va; bRow += vb;
                    aCol[q] += va; bCol[q] += vb;
                }
                aRow += __shfl_xor_sync(0xffffffffu, aRow, 1);
                aRow += __shfl_xor_sync(0xffffffffu, aRow, 2);
                bRow += __shfl_xor_sync(0xffffffffu, bRow, 1);
                bRow += __shfl_xor_sync(0xffffffffu, bRow, 2);
                if (quad == 0) {
                    atomicAdd(&sAccI[rl], aRow);
                    atomicAdd(&sBccI[rl], bRow);
                }
            }
        }

        if (offdiag) {
            #pragma unroll
            for (int q = 0; q < 8; q++) {
                float a = aCol[q], b = bCol[q];
                #pragma unroll
                for (int o = 4; o <= 16; o <<= 1) {
                    a += __shfl_xor_sync(0xffffffffu, a, o);
                    b += __shfl_xor_sync(0xffffffffu, b, o);
                }
                if (lane < 4) {
                    const int cl = n0 + (q >> 1) * 8 + quad * 2 + (q & 1);
                    atomicAdd(&sAccJ[cl], a);
                    atomicAdd(&sBccJ[cl], b);
                }
            }
        }

        __syncthreads();                            // epilogue smem atomics done

        int nbi = biBlk, nbj = bjBlk;
        if (!last) map_tile(ntile, nbi, nbj);
        const int niBase = nbi * TM;
        const int njBase = nbj * TN;

        if (tid < 128) {
            atomicAdd(&g_A[iBase + tid], sAccI[tid]);
            atomicAdd(&g_B[iBase + tid], sBccI[tid]);
            if (offdiag) {
                atomicAdd(&g_A[jBase + tid], sAccJ[tid]);
                atomicAdd(&g_B[jBase + tid], sBccJ[tid]);
            }
            sAccI[tid] = 0.0f; sBccI[tid] = 0.0f;
            sAccJ[tid] = 0.0f; sBccJ[tid] = 0.0f;
            clsI[tid] = g_cls[niBase + tid];
        } else {
            clsJ[tid - 128] = g_cls[njBase + tid - 128];
        }

        if (last) break;
        tile = ntile; biBlk = nbi; bjBlk = nbj;
        iBase = niBase; jBase = njBase;
        offdiag = (nbi != nbj);
    }
}

// ---------------------------------------------------------------------------
// k_loss: histogram, subtract self term (f16-rounded), empty-set, mean
// ---------------------------------------------------------------------------
__global__ void k_loss(float* __restrict__ out) {
    __shared__ float red[256];
    __shared__ int hist[16];
    const int tid = threadIdx.x;
    if (tid < 16) hist[tid] = 0;
    __syncthreads();
    for (int r = tid; r < N; r += 256) atomicAdd(&hist[g_cls[r] & 15], 1);
    __syncthreads();

    const float MF = __expf(0.5f * INV_T);
    float sum = 0.0f;
    for (int r = tid; r < N; r += 256) {
        int   c   = g_cls[r] & 15;
        int   cnt = hist[c];
        float ssh = __half2float(__float2half_rn(g_selfsim[r]));
        float Bv  = g_B[r] - __expf(-ssh * INV_T);
        float Av  = (N - cnt > 0) ? g_A[r] : 1.0f;
        Bv        = (cnt - 1 > 0) ? Bv : 1.0f;
        sum += log1pf(MF * Av * Bv);
    }
    red[tid] = sum;
    __syncthreads();
    #pragma unroll
    for (int s = 128; s; s >>= 1) {
        if (tid < s) red[tid] += red[tid + s];
        __syncthreads();
    }
    if (tid == 0) out[0] = red[0] / (float)N;
}

// ---------------------------------------------------------------------------
extern "C" void kernel_launch(void* const* d_in, const int* in_sizes, int n_in,
                              void* d_out, int out_size) {
    const float* P = (const float*)d_in[0];
    const void*  y = d_in[1];
    float*     out = (float*)d_out;

    cudaFuncSetAttribute(k_main, cudaFuncAttributeMaxDynamicSharedMemorySize,
                         SMEM_BYTES);

    int sms = 148;
    cudaDeviceGetAttribute(&sms, cudaDevAttrMultiProcessorCount, 0);
    int grid = 2 * sms;
    if (grid > NTILES) grid = NTILES;

    k_norm<<<N / 8, 256>>>(P, y);
    k_main<<<grid, 256, SMEM_BYTES>>>();
    k_loss<<<1, 256>>>(out);
}